// round 4
// baseline (speedup 1.0000x reference)
#include <cuda_runtime.h>
#include <math.h>

// Problem constants
#define BN    64
#define HW    784           // 28*28
#define CN    512
#define S     7             // hw splits per kernel -> grid (64, 7) = 448 blocks
#define HWP   112           // HW / S          (per-block hw span)
#define SUBS  4             // hw subsplits inside a block
#define HWS   28            // HWP / SUBS      (per-thread hw span)
#define HWS4  7             // HWS / 4         (float4 chunks)
#define P     28            // partial depth = S * SUBS

// Scratch for partial argmax (device globals: allocation-free)
// Layout [BN][P][CN]; p = s*4 + sub is ascending in hw-start -> first-occurrence safe.
__device__ float g_pval[BN * P * CN];
__device__ int   g_pidx[BN * P * CN];

// ---------------------------------------------------------------------------
// Kernel A: c-vectorized partial argmax.
// Thread owns channels [c4, c4+4); scans 28 hw positions with float4 loads.
// ---------------------------------------------------------------------------
__global__ void __launch_bounds__(512, 2)
argmax_kernel(const float* __restrict__ x) {
    const int b   = blockIdx.x;
    const int s   = blockIdx.y;
    const int c4  = (threadIdx.x & 127) << 2;   // 0,4,...,508
    const int sub = threadIdx.x >> 7;           // 0..3
    const int hw0 = s * HWP + sub * HWS;

    const float4* __restrict__ xr =
        (const float4*)(x + ((size_t)b * HW + hw0) * CN + c4);

    float4 best = make_float4(-INFINITY, -INFINITY, -INFINITY, -INFINITY);
    int4   bidx = make_int4(hw0, hw0, hw0, hw0);

    #pragma unroll 7
    for (int i = 0; i < HWS; ++i) {
        float4 v = xr[(size_t)i * (CN / 4)];
        int    h = hw0 + i;
        if (v.x > best.x) { best.x = v.x; bidx.x = h; }   // strict > + ascending
        if (v.y > best.y) { best.y = v.y; bidx.y = h; }   // => first occurrence
        if (v.z > best.z) { best.z = v.z; bidx.z = h; }
        if (v.w > best.w) { best.w = v.w; bidx.w = h; }
    }

    const int p = s * SUBS + sub;               // ascending p <=> ascending hw0
    const size_t o = ((size_t)b * P + p) * CN + c4;
    *(float4*)(g_pval + o) = best;
    *(int4*)(g_pidx + o)   = bidx;
}

// ---------------------------------------------------------------------------
// Kernel B: combine 28 partials (coalesced float4/int4, L2-hot slab), then
//   out[b,hw,c] = relu(x[b,hw,c] * t_p[b, idx[b,c], hw])
// All three big streams use 16B accesses: templates float4 along hw,
// x/out float4 along c.
// ---------------------------------------------------------------------------
__global__ void __launch_bounds__(512, 2)
apply_kernel(const float* __restrict__ x,
             const float* __restrict__ tp,
             float* __restrict__ out) {
    const int b   = blockIdx.x;
    const int s   = blockIdx.y;
    const int c4  = (threadIdx.x & 127) << 2;
    const int sub = threadIdx.x >> 7;
    const int hw0 = s * HWP + sub * HWS;

    // ---- combine partials (first-occurrence tie-break preserved) ----
    float4 best = make_float4(-INFINITY, -INFINITY, -INFINITY, -INFINITY);
    int4   idx  = make_int4(0, 0, 0, 0);
    {
        const size_t o0 = (size_t)b * P * CN + c4;
        #pragma unroll 7
        for (int p = 0; p < P; ++p) {
            float4 v = *(const float4*)(g_pval + o0 + (size_t)p * CN);
            int4   j = *(const int4*)(g_pidx + o0 + (size_t)p * CN);
            if (v.x > best.x) { best.x = v.x; idx.x = j.x; }
            if (v.y > best.y) { best.y = v.y; idx.y = j.y; }
            if (v.z > best.z) { best.z = v.z; idx.z = j.z; }
            if (v.w > best.w) { best.w = v.w; idx.w = j.w; }
        }
    }

    // ---- selected template row slices (hw0*4 bytes: 112-mult of 16 ✓) ----
    const size_t tb = (size_t)b * HW;
    const float4* __restrict__ t0 = (const float4*)(tp + (tb + idx.x) * HW + hw0);
    const float4* __restrict__ t1 = (const float4*)(tp + (tb + idx.y) * HW + hw0);
    const float4* __restrict__ t2 = (const float4*)(tp + (tb + idx.z) * HW + hw0);
    const float4* __restrict__ t3 = (const float4*)(tp + (tb + idx.w) * HW + hw0);

    const size_t base = ((size_t)b * HW + hw0) * CN + c4;   // 16B aligned (c4%4==0)

    #pragma unroll
    for (int j = 0; j < HWS4; ++j) {
        // templates: 4 hw values per channel slot
        float4 a0 = t0[j];
        float4 a1 = t1[j];
        float4 a2 = t2[j];
        float4 a3 = t3[j];

        const size_t o = base + (size_t)(4 * j) * CN;
        float4 x0 = *(const float4*)(x + o);
        float4 x1 = *(const float4*)(x + o + CN);
        float4 x2 = *(const float4*)(x + o + 2 * CN);
        float4 x3 = *(const float4*)(x + o + 3 * CN);

        float4 r0, r1, r2, r3;
        r0.x = fmaxf(x0.x * a0.x, 0.f); r0.y = fmaxf(x0.y * a1.x, 0.f);
        r0.z = fmaxf(x0.z * a2.x, 0.f); r0.w = fmaxf(x0.w * a3.x, 0.f);
        r1.x = fmaxf(x1.x * a0.y, 0.f); r1.y = fmaxf(x1.y * a1.y, 0.f);
        r1.z = fmaxf(x1.z * a2.y, 0.f); r1.w = fmaxf(x1.w * a3.y, 0.f);
        r2.x = fmaxf(x2.x * a0.z, 0.f); r2.y = fmaxf(x2.y * a1.z, 0.f);
        r2.z = fmaxf(x2.z * a2.z, 0.f); r2.w = fmaxf(x2.w * a3.z, 0.f);
        r3.x = fmaxf(x3.x * a0.w, 0.f); r3.y = fmaxf(x3.y * a1.w, 0.f);
        r3.z = fmaxf(x3.z * a2.w, 0.f); r3.w = fmaxf(x3.w * a3.w, 0.f);

        *(float4*)(out + o)          = r0;
        *(float4*)(out + o + CN)     = r1;
        *(float4*)(out + o + 2 * CN) = r2;
        *(float4*)(out + o + 3 * CN) = r3;
    }
}

// ---------------------------------------------------------------------------
// Launch: inputs [x, t_p]; output fp32 [64,28,28,512]. Graph-capturable.
// ---------------------------------------------------------------------------
extern "C" void kernel_launch(void* const* d_in, const int* in_sizes, int n_in,
                              void* d_out, int out_size) {
    (void)in_sizes; (void)n_in; (void)out_size;
    const float* x   = (const float*)d_in[0];
    const float* tp  = (const float*)d_in[1];
    float*       out = (float*)d_out;

    dim3 grid(BN, S);
    argmax_kernel<<<grid, 512>>>(x);
    apply_kernel<<<grid, 512>>>(x, tp, out);
}